// round 10
// baseline (speedup 1.0000x reference)
#include <cuda_runtime.h>
#include <math.h>
#include <stdint.h>

// VoxelGrid: B=8 batches, 100^3 grid, 65536 points/batch, 10 output channels.
namespace cfg {
constexpr int   G      = 100;
constexpr int   B      = 8;
constexpr int   PTS    = 65536;
constexpr int   POINTS = B * PTS;          // 524288
constexpr int   VOX    = B * G * G * G;    // 8,000,000
constexpr int   CH     = 10;
constexpr int   WORDS  = VOX / 32;         // 250,000
constexpr int   OUTF4  = VOX * CH / 4;     // 20,000,000
constexpr int   BLK_SCATTER = POINTS / 4 / 256;   // 512
constexpr int   BLK_PATTERN = OUTF4 / 256;        // 78125
}

// Per-voxel 32B accumulator: lo=[x,y,z,f0], hi=[f1,f2,count,pad].
// Statically zeroed at load; voxel_patch restores zeros + clears the bitmap
// each run, so graph replays always start clean.
__device__ __align__(32) float4 g_sums[(size_t)cfg::VOX * 2];
__device__ uint32_t g_mask[cfg::WORDS];

__device__ __forceinline__ void red_add_v4(float4* addr, float a, float b,
                                           float c, float d) {
    asm volatile("red.global.add.v4.f32 [%0], {%1, %2, %3, %4};"
                 :: "l"(addr), "f"(a), "f"(b), "f"(c), "f"(d) : "memory");
}

__device__ __forceinline__ void decode_ijk(int v, int& i, int& j, int& k) {
    // v = ((b*G + i)*G + j)*G + k
    k = v % cfg::G;
    int t = v / cfg::G;
    j = t % cfg::G;
    i = (t / cfg::G) % cfg::G;
}

// ---------------------------------------------------------------------------
// voxel_main: heterogeneous grid.
//   blockIdx < BLK_SCATTER  -> point scatter (4 points/thread)
//   otherwise               -> empty-voxel pattern writer (1 float4/thread)
// The two halves touch disjoint buffers, so the latency-bound atomic half
// rides along under the DRAM-bound 320MB pattern stream.
// ---------------------------------------------------------------------------
__global__ void voxel_main(const float4* __restrict__ xyz4,
                           const float4* __restrict__ feat4,
                           float4* __restrict__ out4) {
    const int bx = blockIdx.x;

    if (bx >= cfg::BLK_SCATTER) {
        // ---------------- pattern writer ----------------
        // Each output float4 falls into one of 5 layouts across a voxel
        // pair (va = 2q even => k even <= 98; vb = va+1 shares i,j, k+1):
        //   p0 zeros | p1 [0,0,i,j]/100 | p2 [k/100,0,0,0]
        //   p3 zeros | p4 [i,j,k+1]/100,0
        int idx = (bx - cfg::BLK_SCATTER) * 256 + threadIdx.x;   // < OUTF4
        int q = idx / 5;
        int p = idx - q * 5;

        float4 r = make_float4(0.f, 0.f, 0.f, 0.f);
        if (p == 1 || p == 2 || p == 4) {
            int i, j, k;
            decode_ijk(2 * q, i, j, k);
            float fi = (float)i * 0.01f;
            float fj = (float)j * 0.01f;
            if (p == 1)      r = make_float4(0.f, 0.f, fi, fj);
            else if (p == 2) r = make_float4((float)k * 0.01f, 0.f, 0.f, 0.f);
            else             r = make_float4(fi, fj, (float)(k + 1) * 0.01f, 0.f);
        }
        out4[idx] = r;
        return;
    }

    // ---------------- scatter ----------------
    int t = bx * 256 + threadIdx.x;              // < POINTS/4
    const float RES = 1.0f / 100.0f;

    float4 c0 = xyz4[3 * t], c1 = xyz4[3 * t + 1], c2 = xyz4[3 * t + 2];
    float4 g0 = feat4[3 * t], g1 = feat4[3 * t + 1], g2 = feat4[3 * t + 2];

    float px[4] = {c0.x, c0.w, c1.z, c2.y};
    float py[4] = {c0.y, c1.x, c1.w, c2.z};
    float pz[4] = {c0.z, c1.y, c2.x, c2.w};
    float fa[4] = {g0.x, g0.w, g1.z, g2.y};
    float fb[4] = {g0.y, g1.x, g1.w, g2.z};
    float fc[4] = {g0.z, g1.y, g2.x, g2.w};

    int batch = t >> 14;   // (4t)/65536; a thread's 4 points share one batch

    #pragma unroll
    for (int n = 0; n < 4; n++) {
        float x = px[n], y = py[n], z = pz[n];
        // idx = floor((c+RES)/RES); interior bins are [1,100], shell dropped.
        int ix = (int)floorf((x + RES) / RES);
        int iy = (int)floorf((y + RES) / RES);
        int iz = (int)floorf((z + RES) / RES);
        if (ix < 1 || ix > cfg::G || iy < 1 || iy > cfg::G ||
            iz < 1 || iz > cfg::G)
            continue;

        int v = (((batch * cfg::G + (ix - 1)) * cfg::G + (iy - 1)) * cfg::G
                 + (iz - 1));
        float4* rec = g_sums + (size_t)v * 2;
        red_add_v4(rec,     x,     y,     z,    fa[n]);
        red_add_v4(rec + 1, fb[n], fc[n], 1.0f, 0.0f);
        atomicOr(&g_mask[v >> 5], 1u << (v & 31));
    }
}

// ---------------------------------------------------------------------------
// voxel_patch: thread per voxel. A warp maps exactly onto one bitmap word
// (broadcast load; empty words cost one LDG for the warp). Occupied lanes
// (~6% overall) load their 32B record with full per-lane MLP, overwrite the
// voxel's 40B output slice, and zero the record. Lane (v&31)==0 clears the
// word. All bytes single-owner -> race-free; the word read precedes the
// clear in the warp's lockstep stream.
// ---------------------------------------------------------------------------
__global__ void voxel_patch(float* __restrict__ out) {
    int v = blockIdx.x * 256 + threadIdx.x;      // < VOX

    uint32_t word = g_mask[v >> 5];
    if (word == 0u) return;

    if ((word >> (v & 31)) & 1u) {
        float4 lo = g_sums[2 * (size_t)v];
        float4 hi = g_sums[2 * (size_t)v + 1];
        float4 z = make_float4(0.f, 0.f, 0.f, 0.f);
        g_sums[2 * (size_t)v]     = z;
        g_sums[2 * (size_t)v + 1] = z;

        float inv = 1.0f / hi.z;                 // count >= 1 here

        int i, j, k;
        decode_ijk(v, i, j, k);

        float2* o2 = reinterpret_cast<float2*>(out + (size_t)v * cfg::CH);
        o2[0] = make_float2(lo.x * inv, lo.y * inv);
        o2[1] = make_float2(lo.z * inv, lo.w * inv);
        o2[2] = make_float2(hi.x * inv, hi.y * inv);
        o2[3] = make_float2((float)i * 0.01f, (float)j * 0.01f);
        o2[4] = make_float2((float)k * 0.01f, 1.0f);
    }

    if ((v & 31) == 0)
        g_mask[v >> 5] = 0u;
}

// ---------------------------------------------------------------------------
extern "C" void kernel_launch(void* const* d_in, const int* in_sizes, int n_in,
                              void* d_out, int out_size) {
    const float4* xyz4  = (const float4*)d_in[0];
    const float4* feat4 = (const float4*)d_in[1];

    voxel_main <<<cfg::BLK_SCATTER + cfg::BLK_PATTERN, 256>>>(
        xyz4, feat4, (float4*)d_out);
    voxel_patch<<<cfg::VOX / 256, 256>>>((float*)d_out);
}

// round 11
// speedup vs baseline: 4.9649x; 4.9649x over previous
#include <cuda_runtime.h>
#include <math.h>
#include <stdint.h>

#define VGRID   100
#define NBATCH  8
#define NPTS    65536
#define NPOINTS (NBATCH * NPTS)                   // 524288
#define NVOX    (NBATCH * VGRID * VGRID * VGRID)  // 8,000,000
#define COUT    10
#define NWORDS  (NVOX / 32)                       // 250,000

// 32B record per voxel: lo=[x,y,z,f0], hi=[f1,f2,cnt,pad].
// Zero at module load; finalize self-cleans (same thread reads then zeroes
// its own record => race-free, graph-replay safe; proven round 2).
__device__ __align__(32) float4 g_acc[(size_t)NVOX * 2];
__device__ uint32_t g_bits[NWORDS];

// ---------------------------------------------------------------------------
// Scatter: 4 points per thread, 6x LDG.128 input loads, 3 atomics per point.
// Binning (verified all rounds): idx = floor((c+RES)/RES), keep [1,100].
// ---------------------------------------------------------------------------
__global__ void scatter_kernel(const float4* __restrict__ coords4,
                               const float4* __restrict__ feats4) {
    int t = blockIdx.x * 256 + threadIdx.x;          // < NPOINTS/4
    const float RES = 1.0f / 100.0f;

    float4 c0 = coords4[3 * t], c1 = coords4[3 * t + 1], c2 = coords4[3 * t + 2];
    float4 g0 = feats4 [3 * t], g1 = feats4 [3 * t + 1], g2 = feats4 [3 * t + 2];

    float cx[4] = {c0.x, c0.w, c1.z, c2.y};
    float cy[4] = {c0.y, c1.x, c1.w, c2.z};
    float cz[4] = {c0.z, c1.y, c2.x, c2.w};
    float fa[4] = {g0.x, g0.w, g1.z, g2.y};
    float fb[4] = {g0.y, g1.x, g1.w, g2.z};
    float fc[4] = {g0.z, g1.y, g2.x, g2.w};

    int b = t >> 14;   // (4t)/65536: a thread's 4 points share one batch

    #pragma unroll
    for (int j = 0; j < 4; j++) {
        float x = cx[j], y = cy[j], z = cz[j];
        int ix = (int)floorf((x + RES) / RES);
        int iy = (int)floorf((y + RES) / RES);
        int iz = (int)floorf((z + RES) / RES);
        if (ix < 1 || ix > VGRID || iy < 1 || iy > VGRID ||
            iz < 1 || iz > VGRID)
            continue;
        int v = (((b * VGRID + (ix - 1)) * VGRID + (iy - 1)) * VGRID + (iz - 1));
        float4* rec = g_acc + (size_t)v * 2;
        asm volatile("red.global.add.v4.f32 [%0], {%1, %2, %3, %4};"
                     :: "l"(rec), "f"(x), "f"(y), "f"(z), "f"(fa[j]) : "memory");
        asm volatile("red.global.add.v4.f32 [%0], {%1, %2, %3, %4};"
                     :: "l"(rec + 1), "f"(fb[j]), "f"(fc[j]), "f"(1.0f), "f"(0.0f)
                     : "memory");
        atomicOr(&g_bits[v >> 5], 1u << (v & 31));
    }
}

// ---------------------------------------------------------------------------
// Finalize: EXACT round-2 structure (measured 86.2us, 3990 GB/s).
// One thread per voxel, 256/block:
//  - bitmap word per warp (broadcast load), gate the record read (~6% hit)
//  - occupied: read 32B record, compute means, zero the record (self-clean)
//  - lane (v&31)==0 clears its bitmap word
//  - stage 10 floats/voxel in smem, write block's 10240B with plain STG.128
// ---------------------------------------------------------------------------
__global__ void finalize_kernel(float* __restrict__ out) {
    __shared__ float sh[256 * COUT];

    int v = blockIdx.x * 256 + threadIdx.x;

    uint32_t word = g_bits[v >> 5];
    bool occ = (word >> (v & 31)) & 1u;

    float m0 = 0.f, m1 = 0.f, m2 = 0.f, m3 = 0.f, m4 = 0.f, m5 = 0.f;
    if (occ) {
        float4* rec = g_acc + (size_t)v * 2;
        float4 a = rec[0];
        float4 b = rec[1];
        float inv = 1.0f / fmaxf(b.z, 1.0f);
        m0 = a.x * inv; m1 = a.y * inv; m2 = a.z * inv;
        m3 = a.w * inv; m4 = b.x * inv; m5 = b.y * inv;
        float4 zero = make_float4(0.f, 0.f, 0.f, 0.f);
        rec[0] = zero;                      // self-clean for next replay
        rec[1] = zero;
    }
    if ((v & 31) == 0 && word != 0u)
        g_bits[v >> 5] = 0u;

    // v = ((b*100 + i)*100 + j)*100 + k
    int k = v % VGRID;
    int t = v / VGRID;
    int j = t % VGRID;
    int i = (t / VGRID) % VGRID;

    float* r = sh + threadIdx.x * COUT;
    r[0] = m0; r[1] = m1; r[2] = m2; r[3] = m3; r[4] = m4; r[5] = m5;
    r[6] = (float)i / 100.0f;
    r[7] = (float)j / 100.0f;
    r[8] = (float)k / 100.0f;
    r[9] = occ ? 1.0f : 0.0f;

    __syncthreads();

    // 2560 floats = 640 float4 per block, plain coalesced 16B stores
    float4* dst = reinterpret_cast<float4*>(out + (size_t)blockIdx.x * 256 * COUT);
    const float4* src = reinterpret_cast<const float4*>(sh);
    #pragma unroll
    for (int q = 0; q < 640; q += 256) {
        int idx = q + threadIdx.x;
        if (idx < 640) dst[idx] = src[idx];
    }
}

// ---------------------------------------------------------------------------
extern "C" void kernel_launch(void* const* d_in, const int* in_sizes, int n_in,
                              void* d_out, int out_size) {
    const float4* coords4 = (const float4*)d_in[0];
    const float4* feats4  = (const float4*)d_in[1];
    float* out = (float*)d_out;

    scatter_kernel <<<NPOINTS / 4 / 256, 256>>>(coords4, feats4);
    finalize_kernel<<<NVOX / 256, 256>>>(out);
}

// round 13
// speedup vs baseline: 5.6512x; 1.1382x over previous
#include <cuda_runtime.h>
#include <math.h>
#include <stdint.h>

// VoxelGrid: 8 batches x 100^3 grid, 65536 pts/batch, 10 output channels.
namespace vg {
constexpr int G     = 100;
constexpr int NB    = 8;
constexpr int PTS   = 65536;
constexpr int NPT   = NB * PTS;            // 524288
constexpr int NV    = NB * G * G * G;      // 8,000,000
constexpr int CH    = 10;
constexpr int NW    = NV / 32;             // 250,000 bitmap words
}

// Per-voxel 32B accumulator: lo=[x,y,z,f0], hi=[f1,f2,count,pad].
// Statically zero at load; the output pass self-cleans records + bitmap,
// so every graph replay starts from a clean state.
__device__ __align__(32) float4 g_rec[(size_t)vg::NV * 2];
__device__ uint32_t g_occ[vg::NW];

__device__ __forceinline__ void vred4(float4* a, float p, float q,
                                      float r, float s) {
    asm volatile("red.global.add.v4.f32 [%0], {%1, %2, %3, %4};"
                 :: "l"(a), "f"(p), "f"(q), "f"(r), "f"(s) : "memory");
}

// ---------------------------------------------------------------------------
// Pass 1 — accumulate: 4 points/thread (6x LDG.128), 3 atomics/point.
// Binning: idx = floor((c+R)/R) with R=0.01f; interior bins [1,100] kept,
// boundary shell dropped (matches reference slicing). Verified all rounds.
// ---------------------------------------------------------------------------
__global__ void vg_accumulate(const float4* __restrict__ xyz,
                              const float4* __restrict__ ftr) {
    int t = blockIdx.x * 256 + threadIdx.x;          // < NPT/4
    const float R = 1.0f / 100.0f;

    float4 a0 = xyz[3 * t], a1 = xyz[3 * t + 1], a2 = xyz[3 * t + 2];
    float4 b0 = ftr[3 * t], b1 = ftr[3 * t + 1], b2 = ftr[3 * t + 2];

    float X[4] = {a0.x, a0.w, a1.z, a2.y};
    float Y[4] = {a0.y, a1.x, a1.w, a2.z};
    float Z[4] = {a0.z, a1.y, a2.x, a2.w};
    float F[4] = {b0.x, b0.w, b1.z, b2.y};
    float G_[4] = {b0.y, b1.x, b1.w, b2.z};
    float H[4] = {b0.z, b1.y, b2.x, b2.w};

    int bat = t >> 14;   // a thread's 4 points never straddle a batch

    #pragma unroll
    for (int n = 0; n < 4; n++) {
        float x = X[n], y = Y[n], z = Z[n];
        int ix = (int)floorf((x + R) / R);
        int iy = (int)floorf((y + R) / R);
        int iz = (int)floorf((z + R) / R);
        if (ix < 1 || ix > vg::G || iy < 1 || iy > vg::G ||
            iz < 1 || iz > vg::G)
            continue;
        int v = (((bat * vg::G + (ix - 1)) * vg::G + (iy - 1)) * vg::G
                 + (iz - 1));
        float4* rec = g_rec + (size_t)v * 2;
        vred4(rec,     x,     y,     z,    F[n]);
        vred4(rec + 1, G_[n], H[n], 1.0f, 0.0f);
        atomicOr(&g_occ[v >> 5], 1u << (v & 31));
    }
}

// ---------------------------------------------------------------------------
// Pass 2 — emit: warp-autonomous. Each warp owns 32 voxels = one bitmap
// word (aligned). Occupied lanes read + zero their record; lane 0 clears
// the word. The warp stages its 320 floats in a private smem slice, does a
// __syncwarp (NO block barrier), then streams 80 coalesced float4
// (10 full 128B lines). Warps drain independently, so one warp's scattered
// record-load latency never stalls another warp's store stream.
// ---------------------------------------------------------------------------
__global__ void vg_emit(float* __restrict__ out) {
    __shared__ float stage[256 * vg::CH];

    const int lane = threadIdx.x & 31;
    const int wrp  = threadIdx.x >> 5;
    const int v    = blockIdx.x * 256 + threadIdx.x;

    uint32_t word = g_occ[v >> 5];
    bool occ = (word >> lane) & 1u;

    float m0 = 0.f, m1 = 0.f, m2 = 0.f, m3 = 0.f, m4 = 0.f, m5 = 0.f;
    if (occ) {
        float4* rec = g_rec + (size_t)v * 2;
        float4 lo = rec[0];
        float4 hi = rec[1];
        float inv = 1.0f / hi.z;            // occupied => count >= 1
        m0 = lo.x * inv; m1 = lo.y * inv; m2 = lo.z * inv;
        m3 = lo.w * inv; m4 = hi.x * inv; m5 = hi.y * inv;
        float4 zz = make_float4(0.f, 0.f, 0.f, 0.f);
        rec[0] = zz;                        // self-clean for next replay
        rec[1] = zz;
    }
    if (lane == 0 && word != 0u)
        g_occ[v >> 5] = 0u;

    // v = ((b*100 + i)*100 + j)*100 + k
    int k = v % vg::G;
    int t = v / vg::G;
    int j = t % vg::G;
    int i = (t / vg::G) % vg::G;

    float* s = stage + threadIdx.x * vg::CH;
    s[0] = m0; s[1] = m1; s[2] = m2; s[3] = m3; s[4] = m4; s[5] = m5;
    s[6] = (float)i * 0.01f;
    s[7] = (float)j * 0.01f;
    s[8] = (float)k * 0.01f;
    s[9] = occ ? 1.0f : 0.0f;

    __syncwarp();

    const float4* src = reinterpret_cast<const float4*>(stage) + wrp * 80;
    float4* dst = reinterpret_cast<float4*>(out)
                + (size_t)blockIdx.x * 640 + wrp * 80;
    #pragma unroll
    for (int q = lane; q < 80; q += 32)
        dst[q] = src[q];
}

// ---------------------------------------------------------------------------
extern "C" void kernel_launch(void* const* d_in, const int* in_sizes, int n_in,
                              void* d_out, int out_size) {
    const float4* xyz = (const float4*)d_in[0];
    const float4* ftr = (const float4*)d_in[1];

    vg_accumulate<<<vg::NPT / 4 / 256, 256>>>(xyz, ftr);
    vg_emit      <<<vg::NV / 256, 256>>>((float*)d_out);
}